// round 7
// baseline (speedup 1.0000x reference)
#include <cuda_runtime.h>

#define C_CH 32
#define HW   256
#define KS2  9
#define OCH  288
#define QS   32
#define NB   4

__device__ float g_p[NB * C_CH * QS * QS];   // [n][c][32][32]
__device__ float g_y[NB * OCH * QS * QS];    // [n][o][32][32]

// ---------------------------------------------------------------------------
// Kernel A: psf -> bilinear 1/4 -> maxpool2 -> g_p. (invariant ~7.3us: DRAM
// 2KB-granular row pattern caps effective bandwidth; leave alone)
// ---------------------------------------------------------------------------
__global__ void __launch_bounds__(256) kA(const float* __restrict__ psf) {
    const int b  = blockIdx.x;
    const int it = b & 7;
    const int c  = (b >> 3) & 31;
    const int n  = b >> 8;
    const int tid  = threadIdx.x;
    const int warp = tid >> 5;
    const int lane = tid & 31;
    const int ii   = warp >> 1;
    const int half = warp & 1;
    const int i = it * 4 + ii;

    const float4* base = (const float4*)(psf + ((size_t)(n * C_CH + c) * HW) * HW);
    const int r0 = 8 * i + 1 + 4 * half;
    const float4* p0 = base + r0 * (HW / 4);
    const float4* p1 = p0 + (HW / 4);

    float4 a0 = __ldg(p0 + lane);
    float4 a1 = __ldg(p0 + 32 + lane);
    float4 b0 = __ldg(p1 + lane);
    float4 b1 = __ldg(p1 + 32 + lane);

    float slo = (a0.y + a0.z) + (b0.y + b0.z);
    float shi = (a1.y + a1.z) + (b1.y + b1.z);
    slo = fmaxf(slo, __shfl_xor_sync(0xffffffffu, slo, 1));
    shi = fmaxf(shi, __shfl_xor_sync(0xffffffffu, shi, 1));

    __shared__ float sm[2][4][32];
    if ((lane & 1) == 0) {
        int j = lane >> 1;
        sm[half][ii][j]      = slo;
        sm[half][ii][j + 16] = shi;
    }
    __syncthreads();

    if (tid < 128) {
        int j  = tid & 31;
        int iw = tid >> 5;
        float m = fmaxf(sm[0][iw][j], sm[1][iw][j]);
        g_p[((size_t)(n * C_CH + c) * QS + it * 4 + iw) * QS + j] = 0.25f * m;
    }
}

// ---------------------------------------------------------------------------
// Kernel B: thread = (n, o, pix). (R1/R6 version — in the best run)
// ---------------------------------------------------------------------------
__global__ void kB(const float* __restrict__ w1, const float* __restrict__ b1,
                   const float* __restrict__ ws, const float* __restrict__ bs) {
    int t = blockIdx.x * blockDim.x + threadIdx.x;   // 4*288*1024
    int pix = t & 1023;
    int o = (t >> 10) % OCH;
    int n = t / (1024 * OCH);
    const float* pbase = g_p + (size_t)(n * C_CH) * (QS * QS) + pix;
    float a1 = 0.f, a2 = 0.f;
#pragma unroll
    for (int c = 0; c < C_CH; c++) {
        float pv = pbase[c * (QS * QS)];
        a1 = fmaf(pv, w1[o * C_CH + c], a1);
        a2 = fmaf(pv, ws[o * C_CH + c], a2);
    }
    a1 += b1[o];
    a2 += bs[o];
    float act = (a1 >= 0.f) ? a1 : 0.2f * a1;
    g_y[t] = act + a2;
}

// ---------------------------------------------------------------------------
// Pad kernel: keeps the ncu capture slot on kC.
// ---------------------------------------------------------------------------
__global__ void kPad() {}

// ---------------------------------------------------------------------------
// Kernel C: R6 structure + tap-contiguous yt[r][col][12] so each hl corner
// load is 2x LDS.128 + 1x LDS.32 (hl LDS: 72 -> 24 instructions).
// ---------------------------------------------------------------------------
__global__ void __launch_bounds__(256) kC(const float* __restrict__ fm,
                                          float* __restrict__ out) {
    __shared__ float fmt[18][258];
    __shared__ __align__(16) float yt[4][32][12];  // [coarse row][col][tap(+pad)]

    const int tt = blockIdx.x;           // 0..15
    const int c  = blockIdx.y;
    const int n  = blockIdx.z;
    const int w  = threadIdx.x;
    const int h0 = tt * 16;
    const int crBase = 2 * tt - 1;

    // ---- stage featuremap tile ----
    const float* fbase = fm + ((size_t)(n * C_CH + c) * HW) * HW;
#pragma unroll
    for (int r = 0; r < 18; r++) {
        int gh = h0 - 1 + r;
        bool rowok = (gh >= 0) && (gh < HW);
        int gw = w - 1;
        fmt[r][w] = (rowok && gw >= 0) ? fbase[gh * HW + gw] : 0.f;
        if (w < 2) {
            int gw2 = 255 + w;
            fmt[r][256 + w] = (rowok && gw2 < HW) ? fbase[gh * HW + gw2] : 0.f;
        }
    }

    // ---- stage coarse filter rows (row-clamped), tap-contiguous layout ----
    const float* ybase = g_y + (size_t)(n * OCH + c * KS2) * (QS * QS);
    for (int idx = w; idx < 4 * KS2 * 32; idx += 256) {
        int col = idx & 31;                  // coalesced global reads over col
        int q = idx >> 5;                    // 0..35
        int r = q / KS2;
        int k = q - r * KS2;
        int cr = min(max(crBase + r, 0), QS - 1);
        yt[r][col][k] = ybase[k * (QS * QS) + cr * QS + col];
    }
    __syncthreads();

    // ---- horizontal lerp: rolling lo/diff, vectorized smem reads ----
    int ix0 = (w - 4) >> 3;
    float wx = (float)w * 0.125f - 0.4375f - (float)ix0;
    const int jx0 = max(ix0, 0);
    const int jx1 = min(ix0 + 1, QS - 1);

    auto loadHL = [&](int r, float* dst) {
        const float4* pa = (const float4*)yt[r][jx0];
        const float4* pb = (const float4*)yt[r][jx1];
        float4 a0 = pa[0], a1 = pa[1];
        float4 b0 = pb[0], b1 = pb[1];
        float  a8 = yt[r][jx0][8];
        float  b8 = yt[r][jx1][8];
        dst[0] = fmaf(wx, b0.x - a0.x, a0.x);
        dst[1] = fmaf(wx, b0.y - a0.y, a0.y);
        dst[2] = fmaf(wx, b0.z - a0.z, a0.z);
        dst[3] = fmaf(wx, b0.w - a0.w, a0.w);
        dst[4] = fmaf(wx, b1.x - a1.x, a1.x);
        dst[5] = fmaf(wx, b1.y - a1.y, a1.y);
        dst[6] = fmaf(wx, b1.z - a1.z, a1.z);
        dst[7] = fmaf(wx, b1.w - a1.w, a1.w);
        dst[8] = fmaf(wx, b8 - a8, a8);
    };

    float hlLo[KS2], diff[KS2];
    loadHL(0, hlLo);
    loadHL(1, diff);
#pragma unroll
    for (int k = 0; k < KS2; k++) diff[k] -= hlLo[k];

    auto advance = [&](int newRow) {
#pragma unroll
        for (int k = 0; k < KS2; k++) hlLo[k] += diff[k];
        loadHL(newRow, diff);
#pragma unroll
        for (int k = 0; k < KS2; k++) diff[k] -= hlLo[k];
    };

    // ---- rolling 3x3 window + FAC ----
    float win[3][3];
#pragma unroll
    for (int d = 0; d < 3; d++) {
        win[0][d] = fmt[0][w + d];
        win[1][d] = fmt[1][w + d];
    }

    float* obase = out + (((size_t)(n * C_CH + c) * HW + h0) * HW) + w;

    auto doRow = [&](int hh, float wy) {
#pragma unroll
        for (int d = 0; d < 3; d++) win[2][d] = fmt[hh + 2][w + d];
        float accA = 0.f, accB = 0.f;
#pragma unroll
        for (int dy = 0; dy < 3; dy++) {
#pragma unroll
            for (int dx = 0; dx < 3; dx++) {
                int k = dy * 3 + dx;
                float ft = fmaf(wy, diff[k], hlLo[k]);
                if (k < 5) accA = fmaf(ft, win[dy][dx], accA);
                else       accB = fmaf(ft, win[dy][dx], accB);
            }
        }
        obase[hh * HW] = accA + accB;
#pragma unroll
        for (int d = 0; d < 3; d++) {
            win[0][d] = win[1][d];
            win[1][d] = win[2][d];
        }
    };

#pragma unroll
    for (int hh = 0; hh < 4; hh++)   doRow(hh, (float)hh * 0.125f + 0.5625f);
    advance(2);
#pragma unroll
    for (int hh = 4; hh < 12; hh++)  doRow(hh, (float)hh * 0.125f - 0.4375f);
    advance(3);
#pragma unroll
    for (int hh = 12; hh < 16; hh++) doRow(hh, (float)hh * 0.125f - 1.4375f);
}

// ---------------------------------------------------------------------------
extern "C" void kernel_launch(void* const* d_in, const int* in_sizes, int n_in,
                              void* d_out, int out_size) {
    const float* psf = (const float*)d_in[0];
    const float* fm  = (const float*)d_in[1];
    const float* w1  = (const float*)d_in[2];
    const float* b1  = (const float*)d_in[3];
    const float* ws  = (const float*)d_in[4];
    const float* bs  = (const float*)d_in[5];
    float* out = (float*)d_out;

    kA<<<1024, 256>>>(psf);
    kB<<<4608, 256>>>(w1, b1, ws, bs);
    kPad<<<1, 32>>>();
    dim3 gc(16, C_CH, NB);
    kC<<<gc, 256>>>(fm, out);
}

// round 9
// speedup vs baseline: 1.3035x; 1.3035x over previous
#include <cuda_runtime.h>

#define C_CH 32
#define HW   256
#define KS2  9
#define OCH  288
#define QS   32
#define NB   4

#define FSTR 264   // fmt row stride (words); interior cols 4..259 (16B aligned)

__device__ float g_p[NB * C_CH * QS * QS];   // [n][c][32][32]
__device__ float g_y[NB * OCH * QS * QS];    // [n][o][32][32]

// ---------------------------------------------------------------------------
// Kernel A: psf -> bilinear 1/4 -> maxpool2 -> g_p  (R5/R7 version)
// ---------------------------------------------------------------------------
__global__ void __launch_bounds__(256) kA(const float* __restrict__ psf) {
    const int b  = blockIdx.x;
    const int it = b & 7;
    const int c  = (b >> 3) & 31;
    const int n  = b >> 8;
    const int tid  = threadIdx.x;
    const int warp = tid >> 5;
    const int lane = tid & 31;
    const int ii   = warp >> 1;
    const int half = warp & 1;
    const int i = it * 4 + ii;

    const float4* base = (const float4*)(psf + ((size_t)(n * C_CH + c) * HW) * HW);
    const int r0 = 8 * i + 1 + 4 * half;
    const float4* p0 = base + r0 * (HW / 4);
    const float4* p1 = p0 + (HW / 4);

    float4 a0 = __ldg(p0 + lane);
    float4 a1 = __ldg(p0 + 32 + lane);
    float4 b0 = __ldg(p1 + lane);
    float4 b1 = __ldg(p1 + 32 + lane);

    float slo = (a0.y + a0.z) + (b0.y + b0.z);
    float shi = (a1.y + a1.z) + (b1.y + b1.z);
    slo = fmaxf(slo, __shfl_xor_sync(0xffffffffu, slo, 1));
    shi = fmaxf(shi, __shfl_xor_sync(0xffffffffu, shi, 1));

    __shared__ float sm[2][4][32];
    if ((lane & 1) == 0) {
        int j = lane >> 1;
        sm[half][ii][j]      = slo;
        sm[half][ii][j + 16] = shi;
    }
    __syncthreads();

    if (tid < 128) {
        int j  = tid & 31;
        int iw = tid >> 5;
        float m = fmaxf(sm[0][iw][j], sm[1][iw][j]);
        g_p[((size_t)(n * C_CH + c) * QS + it * 4 + iw) * QS + j] = 0.25f * m;
    }
}

// ---------------------------------------------------------------------------
// Kernel B: thread = (n, o, pix)  (R1/R6/R7 version — in the best run)
// ---------------------------------------------------------------------------
__global__ void kB(const float* __restrict__ w1, const float* __restrict__ b1,
                   const float* __restrict__ ws, const float* __restrict__ bs) {
    int t = blockIdx.x * blockDim.x + threadIdx.x;   // 4*288*1024
    int pix = t & 1023;
    int o = (t >> 10) % OCH;
    int n = t / (1024 * OCH);
    const float* pbase = g_p + (size_t)(n * C_CH) * (QS * QS) + pix;
    float a1 = 0.f, a2 = 0.f;
#pragma unroll
    for (int c = 0; c < C_CH; c++) {
        float pv = pbase[c * (QS * QS)];
        a1 = fmaf(pv, w1[o * C_CH + c], a1);
        a2 = fmaf(pv, ws[o * C_CH + c], a2);
    }
    a1 += b1[o];
    a2 += bs[o];
    float act = (a1 >= 0.f) ? a1 : 0.2f * a1;
    g_y[t] = act + a2;
}

__global__ void kPad() {}

// ---------------------------------------------------------------------------
// Kernel C: R7 structure, but fmt staged with float4 (stride-264 layout,
// interior at col offset 4; halo cols 3 and 260 are always-zero pads).
// ---------------------------------------------------------------------------
__global__ void __launch_bounds__(256) kC(const float* __restrict__ fm,
                                          float* __restrict__ out) {
    __shared__ float fmt[18 * FSTR];
    __shared__ __align__(16) float yt[4][32][12];

    const int tt = blockIdx.x;           // 0..15
    const int c  = blockIdx.y;
    const int n  = blockIdx.z;
    const int w  = threadIdx.x;
    const int h0 = tt * 16;
    const int crBase = 2 * tt - 1;

    // ---- stage featuremap tile, vectorized ----
    const float4* fbase4 = (const float4*)(fm + ((size_t)(n * C_CH + c) * HW) * HW);
    const float4 z4 = make_float4(0.f, 0.f, 0.f, 0.f);
#pragma unroll
    for (int v = 0; v < 5; v++) {
        int idx = v * 256 + w;           // 0..1279; need < 1152
        if (idx < 18 * 64) {
            int r = idx >> 6;
            int q = idx & 63;
            int gh = h0 - 1 + r;
            float4 val = (gh >= 0 && gh < HW) ? __ldg(fbase4 + gh * (HW / 4) + q) : z4;
            *(float4*)&fmt[r * FSTR + 4 + 4 * q] = val;
        }
    }
    // always-zero halo columns (gw = -1 and gw = 256)
    if (w < 36) {
        int r = w >> 1;
        fmt[r * FSTR + 3 + 257 * (w & 1)] = 0.f;
    }

    // ---- stage coarse filter rows (row-clamped), tap-contiguous ----
    const float* ybase = g_y + (size_t)(n * OCH + c * KS2) * (QS * QS);
    for (int idx = w; idx < 4 * KS2 * 32; idx += 256) {
        int col = idx & 31;
        int q = idx >> 5;
        int r = q / KS2;
        int k = q - r * KS2;
        int cr = min(max(crBase + r, 0), QS - 1);
        yt[r][col][k] = ybase[k * (QS * QS) + cr * QS + col];
    }
    __syncthreads();

    // ---- horizontal lerp: rolling lo/diff, vectorized smem reads ----
    int ix0 = (w - 4) >> 3;
    float wx = (float)w * 0.125f - 0.4375f - (float)ix0;
    const int jx0 = max(ix0, 0);
    const int jx1 = min(ix0 + 1, QS - 1);

    auto loadHL = [&](int r, float* dst) {
        const float4* pa = (const float4*)yt[r][jx0];
        const float4* pb = (const float4*)yt[r][jx1];
        float4 a0 = pa[0], a1 = pa[1];
        float4 b0 = pb[0], b1 = pb[1];
        float  a8 = yt[r][jx0][8];
        float  b8 = yt[r][jx1][8];
        dst[0] = fmaf(wx, b0.x - a0.x, a0.x);
        dst[1] = fmaf(wx, b0.y - a0.y, a0.y);
        dst[2] = fmaf(wx, b0.z - a0.z, a0.z);
        dst[3] = fmaf(wx, b0.w - a0.w, a0.w);
        dst[4] = fmaf(wx, b1.x - a1.x, a1.x);
        dst[5] = fmaf(wx, b1.y - a1.y, a1.y);
        dst[6] = fmaf(wx, b1.z - a1.z, a1.z);
        dst[7] = fmaf(wx, b1.w - a1.w, a1.w);
        dst[8] = fmaf(wx, b8 - a8, a8);
    };

    float hlLo[KS2], diff[KS2];
    loadHL(0, hlLo);
    loadHL(1, diff);
#pragma unroll
    for (int k = 0; k < KS2; k++) diff[k] -= hlLo[k];

    auto advance = [&](int newRow) {
#pragma unroll
        for (int k = 0; k < KS2; k++) hlLo[k] += diff[k];
        loadHL(newRow, diff);
#pragma unroll
        for (int k = 0; k < KS2; k++) diff[k] -= hlLo[k];
    };

    // ---- rolling 3x3 window + FAC ----
    const float* fcol = fmt + (w + 3);   // fmt[r][w+3+d], d=0..2
    float win[3][3];
#pragma unroll
    for (int d = 0; d < 3; d++) {
        win[0][d] = fcol[0 * FSTR + d];
        win[1][d] = fcol[1 * FSTR + d];
    }

    float* obase = out + (((size_t)(n * C_CH + c) * HW + h0) * HW) + w;

    auto doRow = [&](int hh, float wy) {
#pragma unroll
        for (int d = 0; d < 3; d++) win[2][d] = fcol[(hh + 2) * FSTR + d];
        float accA = 0.f, accB = 0.f;
#pragma unroll
        for (int dy = 0; dy < 3; dy++) {
#pragma unroll
            for (int dx = 0; dx < 3; dx++) {
                int k = dy * 3 + dx;
                float ft = fmaf(wy, diff[k], hlLo[k]);
                if (k < 5) accA = fmaf(ft, win[dy][dx], accA);
                else       accB = fmaf(ft, win[dy][dx], accB);
            }
        }
        obase[hh * HW] = accA + accB;
#pragma unroll
        for (int d = 0; d < 3; d++) {
            win[0][d] = win[1][d];
            win[1][d] = win[2][d];
        }
    };

#pragma unroll
    for (int hh = 0; hh < 4; hh++)   doRow(hh, (float)hh * 0.125f + 0.5625f);
    advance(2);
#pragma unroll
    for (int hh = 4; hh < 12; hh++)  doRow(hh, (float)hh * 0.125f - 0.4375f);
    advance(3);
#pragma unroll
    for (int hh = 12; hh < 16; hh++) doRow(hh, (float)hh * 0.125f - 1.4375f);
}

// ---------------------------------------------------------------------------
extern "C" void kernel_launch(void* const* d_in, const int* in_sizes, int n_in,
                              void* d_out, int out_size) {
    const float* psf = (const float*)d_in[0];
    const float* fm  = (const float*)d_in[1];
    const float* w1  = (const float*)d_in[2];
    const float* b1  = (const float*)d_in[3];
    const float* ws  = (const float*)d_in[4];
    const float* bs  = (const float*)d_in[5];
    float* out = (float*)d_out;

    kA<<<1024, 256>>>(psf);
    kB<<<4608, 256>>>(w1, b1, ws, bs);
    kPad<<<1, 32>>>();
    dim3 gc(16, C_CH, NB);
    kC<<<gc, 256>>>(fm, out);
}

// round 10
// speedup vs baseline: 1.4452x; 1.1087x over previous
#include <cuda_runtime.h>

#define C_CH 32
#define HW   256
#define KS2  9
#define OCH  288
#define QS   32
#define NB   4

#define FSTR 264   // fmt row stride (words); interior cols 4..259 (16B aligned)

__device__ float g_p[NB * C_CH * QS * QS];   // [n][c][32][32]
__device__ float g_y[NB * OCH * QS * QS];    // [n][o][32][32]

// ---- f32x2 packed helpers (sm_103a native) ----
typedef unsigned long long u64;
__device__ __forceinline__ u64 pk2(float lo, float hi) {
    u64 r; asm("mov.b64 %0, {%1, %2};" : "=l"(r) : "f"(lo), "f"(hi)); return r;
}
__device__ __forceinline__ float2 unpk2(u64 v) {
    float2 f; asm("mov.b64 {%0, %1}, %2;" : "=f"(f.x), "=f"(f.y) : "l"(v)); return f;
}
__device__ __forceinline__ u64 ffma2(u64 a, u64 b, u64 c) {
    u64 d; asm("fma.rn.f32x2 %0, %1, %2, %3;" : "=l"(d) : "l"(a), "l"(b), "l"(c)); return d;
}
__device__ __forceinline__ u64 fadd2(u64 a, u64 b) {
    u64 d; asm("add.rn.f32x2 %0, %1, %2;" : "=l"(d) : "l"(a), "l"(b)); return d;
}
__device__ __forceinline__ u64 fneg2(u64 a) { return a ^ 0x8000000080000000ULL; }

// ---------------------------------------------------------------------------
// Kernel A: psf -> bilinear 1/4 -> maxpool2 -> g_p  (R9 version, unchanged)
// ---------------------------------------------------------------------------
__global__ void __launch_bounds__(256) kA(const float* __restrict__ psf) {
    const int b  = blockIdx.x;
    const int it = b & 7;
    const int c  = (b >> 3) & 31;
    const int n  = b >> 8;
    const int tid  = threadIdx.x;
    const int warp = tid >> 5;
    const int lane = tid & 31;
    const int ii   = warp >> 1;
    const int half = warp & 1;
    const int i = it * 4 + ii;

    const float4* base = (const float4*)(psf + ((size_t)(n * C_CH + c) * HW) * HW);
    const int r0 = 8 * i + 1 + 4 * half;
    const float4* p0 = base + r0 * (HW / 4);
    const float4* p1 = p0 + (HW / 4);

    float4 a0 = __ldg(p0 + lane);
    float4 a1 = __ldg(p0 + 32 + lane);
    float4 b0 = __ldg(p1 + lane);
    float4 b1 = __ldg(p1 + 32 + lane);

    float slo = (a0.y + a0.z) + (b0.y + b0.z);
    float shi = (a1.y + a1.z) + (b1.y + b1.z);
    slo = fmaxf(slo, __shfl_xor_sync(0xffffffffu, slo, 1));
    shi = fmaxf(shi, __shfl_xor_sync(0xffffffffu, shi, 1));

    __shared__ float sm[2][4][32];
    if ((lane & 1) == 0) {
        int j = lane >> 1;
        sm[half][ii][j]      = slo;
        sm[half][ii][j + 16] = shi;
    }
    __syncthreads();

    if (tid < 128) {
        int j  = tid & 31;
        int iw = tid >> 5;
        float m = fmaxf(sm[0][iw][j], sm[1][iw][j]);
        g_p[((size_t)(n * C_CH + c) * QS + it * 4 + iw) * QS + j] = 0.25f * m;
    }
}

// ---------------------------------------------------------------------------
// Kernel B: thread = (n, o, pix)  (R9 version, unchanged)
// ---------------------------------------------------------------------------
__global__ void kB(const float* __restrict__ w1, const float* __restrict__ b1,
                   const float* __restrict__ ws, const float* __restrict__ bs) {
    int t = blockIdx.x * blockDim.x + threadIdx.x;   // 4*288*1024
    int pix = t & 1023;
    int o = (t >> 10) % OCH;
    int n = t / (1024 * OCH);
    const float* pbase = g_p + (size_t)(n * C_CH) * (QS * QS) + pix;
    float a1 = 0.f, a2 = 0.f;
#pragma unroll
    for (int c = 0; c < C_CH; c++) {
        float pv = pbase[c * (QS * QS)];
        a1 = fmaf(pv, w1[o * C_CH + c], a1);
        a2 = fmaf(pv, ws[o * C_CH + c], a2);
    }
    a1 += b1[o];
    a2 += bs[o];
    float act = (a1 >= 0.f) ? a1 : 0.2f * a1;
    g_y[t] = act + a2;
}

__global__ void kPad() {}

// ---------------------------------------------------------------------------
// Kernel C: fused x8 bilinear upsample + FAC. 128 threads; thread j owns the
// column pair (2j, 2j+1). Both columns share jx0/jx1 (provable), weights
// differ by exactly 0.125, so hl/diff/window/acc are f32x2-packed: 18 FFMA2
// produce 2 outputs (was 18 FFMA per output pair x2).
// ---------------------------------------------------------------------------
__global__ void __launch_bounds__(128) kC(const float* __restrict__ fm,
                                          float* __restrict__ out) {
    __shared__ float fmt[18 * FSTR];
    __shared__ __align__(16) float yt[4][32][12];  // [coarse row][col][tap+pad]

    const int tt = blockIdx.x;           // 0..15
    const int c  = blockIdx.y;
    const int n  = blockIdx.z;
    const int j  = threadIdx.x;          // 0..127, columns (2j, 2j+1)
    const int h0 = tt * 16;
    const int crBase = 2 * tt - 1;

    // ---- stage featuremap tile, vectorized: 1152 float4 = 9 per thread ----
    const float4* fbase4 = (const float4*)(fm + ((size_t)(n * C_CH + c) * HW) * HW);
    const float4 z4 = make_float4(0.f, 0.f, 0.f, 0.f);
#pragma unroll
    for (int v = 0; v < 9; v++) {
        int idx = v * 128 + j;           // exactly 18*64
        int r = idx >> 6;
        int q = idx & 63;
        int gh = h0 - 1 + r;
        float4 val = (gh >= 0 && gh < HW) ? __ldg(fbase4 + gh * (HW / 4) + q) : z4;
        *(float4*)&fmt[r * FSTR + 4 + 4 * q] = val;
    }
    // always-zero halo columns (gw = -1 and gw = 256)
    if (j < 36) {
        int r = j >> 1;
        fmt[r * FSTR + 3 + 257 * (j & 1)] = 0.f;
    }

    // ---- stage coarse filter rows (row-clamped), tap-contiguous ----
    // 4 rows x 9 taps x 32 cols = 288 float4 source reads
    const float* ybase = g_y + (size_t)(n * OCH + c * KS2) * (QS * QS);
#pragma unroll
    for (int v = 0; v < 3; v++) {
        int idx = v * 128 + j;
        if (idx < 288) {
            int q  = idx & 7;            // float4 index within 32-col row
            int rk = idx >> 3;           // 0..35
            int r  = rk / KS2;
            int k  = rk - r * KS2;
            int cr = min(max(crBase + r, 0), QS - 1);
            float4 s = __ldg((const float4*)(ybase + k * (QS * QS) + cr * QS) + q);
            int col = 4 * q;
            yt[r][col + 0][k] = s.x;
            yt[r][col + 1][k] = s.y;
            yt[r][col + 2][k] = s.z;
            yt[r][col + 3][k] = s.w;
        }
    }
    __syncthreads();

    // ---- horizontal lerp, packed over the column pair ----
    const int c0 = 2 * j;
    int ix0 = (c0 - 4) >> 3;
    float wx0 = (float)c0 * 0.125f - 0.4375f - (float)ix0;
    float wx1 = wx0 + 0.125f;
    const int jx0 = max(ix0, 0);
    const int jx1 = min(ix0 + 1, QS - 1);

    u64 hl2[KS2], df2[KS2];
    auto loadHL2 = [&](int r, u64* dst) {
        const float4* pa = (const float4*)yt[r][jx0];
        const float4* pb = (const float4*)yt[r][jx1];
        float4 a0 = pa[0], a1 = pa[1];
        float4 b0 = pb[0], b1 = pb[1];
        float  a8 = yt[r][jx0][8];
        float  b8 = yt[r][jx1][8];
        float ta[KS2];
        ta[0] = b0.x - a0.x; ta[1] = b0.y - a0.y; ta[2] = b0.z - a0.z;
        ta[3] = b0.w - a0.w; ta[4] = b1.x - a1.x; ta[5] = b1.y - a1.y;
        ta[6] = b1.z - a1.z; ta[7] = b1.w - a1.w; ta[8] = b8 - a8;
        float av[KS2];
        av[0] = a0.x; av[1] = a0.y; av[2] = a0.z; av[3] = a0.w;
        av[4] = a1.x; av[5] = a1.y; av[6] = a1.z; av[7] = a1.w; av[8] = a8;
#pragma unroll
        for (int k = 0; k < KS2; k++)
            dst[k] = pk2(fmaf(wx0, ta[k], av[k]), fmaf(wx1, ta[k], av[k]));
    };

    loadHL2(0, hl2);
    loadHL2(1, df2);
#pragma unroll
    for (int k = 0; k < KS2; k++) df2[k] = fadd2(df2[k], fneg2(hl2[k]));

    auto advance = [&](int newRow) {
#pragma unroll
        for (int k = 0; k < KS2; k++) hl2[k] = fadd2(hl2[k], df2[k]);
        loadHL2(newRow, df2);
#pragma unroll
        for (int k = 0; k < KS2; k++) df2[k] = fadd2(df2[k], fneg2(hl2[k]));
    };

    // ---- rolling 3x4 window as packs P[dy][dx] = (f[x+dx-1], f[x+dx]) ----
    const float* fcol = fmt + 3 + c0;    // window scalars at [r*FSTR + d], d=0..3
    u64 P[3][3];
#pragma unroll
    for (int r = 0; r < 2; r++) {
        float f0 = fcol[r * FSTR + 0], f1 = fcol[r * FSTR + 1];
        float f2 = fcol[r * FSTR + 2], f3 = fcol[r * FSTR + 3];
        P[r][0] = pk2(f0, f1); P[r][1] = pk2(f1, f2); P[r][2] = pk2(f2, f3);
    }

    float2* ob = (float2*)(out + (((size_t)(n * C_CH + c) * HW + h0) * HW) + c0);

    auto doRow = [&](int hh, float wy) {
        {
            float f0 = fcol[(hh + 2) * FSTR + 0], f1 = fcol[(hh + 2) * FSTR + 1];
            float f2 = fcol[(hh + 2) * FSTR + 2], f3 = fcol[(hh + 2) * FSTR + 3];
            P[2][0] = pk2(f0, f1); P[2][1] = pk2(f1, f2); P[2][2] = pk2(f2, f3);
        }
        u64 wy2 = pk2(wy, wy);
        u64 accA = 0, accB = 0;          // bits 0 == (0.0f, 0.0f)
#pragma unroll
        for (int dy = 0; dy < 3; dy++) {
#pragma unroll
            for (int dx = 0; dx < 3; dx++) {
                int k = dy * 3 + dx;
                u64 ft = ffma2(wy2, df2[k], hl2[k]);
                if (k < 5) accA = ffma2(ft, P[dy][dx], accA);
                else       accB = ffma2(ft, P[dy][dx], accB);
            }
        }
        ob[hh * (HW / 2)] = unpk2(fadd2(accA, accB));
#pragma unroll
        for (int d = 0; d < 3; d++) { P[0][d] = P[1][d]; P[1][d] = P[2][d]; }
    };

#pragma unroll
    for (int hh = 0; hh < 4; hh++)   doRow(hh, (float)hh * 0.125f + 0.5625f);
    advance(2);
#pragma unroll
    for (int hh = 4; hh < 12; hh++)  doRow(hh, (float)hh * 0.125f - 0.4375f);
    advance(3);
#pragma unroll
    for (int hh = 12; hh < 16; hh++) doRow(hh, (float)hh * 0.125f - 1.4375f);
}

// ---------------------------------------------------------------------------
extern "C" void kernel_launch(void* const* d_in, const int* in_sizes, int n_in,
                              void* d_out, int out_size) {
    const float* psf = (const float*)d_in[0];
    const float* fm  = (const float*)d_in[1];
    const float* w1  = (const float*)d_in[2];
    const float* b1  = (const float*)d_in[3];
    const float* ws  = (const float*)d_in[4];
    const float* bs  = (const float*)d_in[5];
    float* out = (float*)d_out;

    kA<<<1024, 256>>>(psf);
    kB<<<4608, 256>>>(w1, b1, ws, bs);
    kPad<<<1, 32>>>();
    dim3 gc(16, C_CH, NB);
    kC<<<gc, 128>>>(fm, out);
}

// round 11
// speedup vs baseline: 2.0264x; 1.4022x over previous
#include <cuda_runtime.h>

#define C_CH 32
#define HW   256
#define KS2  9
#define OCH  288
#define QS   32
#define NB   4

#define FSTR 264   // fmt row stride (words); interior cols 4..259 (16B aligned)

__device__ float g_p[NB * C_CH * QS * QS];   // [n][c][32][32]
__device__ float g_y[NB * OCH * QS * QS];    // [n][o][32][32]

// ---- f32x2 packed helpers (sm_103a native) ----
typedef unsigned long long u64;
__device__ __forceinline__ u64 pk2(float lo, float hi) {
    u64 r; asm("mov.b64 %0, {%1, %2};" : "=l"(r) : "f"(lo), "f"(hi)); return r;
}
__device__ __forceinline__ float2 unpk2(u64 v) {
    float2 f; asm("mov.b64 {%0, %1}, %2;" : "=f"(f.x), "=f"(f.y) : "l"(v)); return f;
}
__device__ __forceinline__ u64 ffma2(u64 a, u64 b, u64 c) {
    u64 d; asm("fma.rn.f32x2 %0, %1, %2, %3;" : "=l"(d) : "l"(a), "l"(b), "l"(c)); return d;
}
__device__ __forceinline__ u64 fadd2(u64 a, u64 b) {
    u64 d; asm("add.rn.f32x2 %0, %1, %2;" : "=l"(d) : "l"(a), "l"(b)); return d;
}
__device__ __forceinline__ u64 fneg2(u64 a) { return a ^ 0x8000000080000000ULL; }

// ---------------------------------------------------------------------------
// Kernel A: psf -> bilinear 1/4 -> maxpool2 -> g_p  (unchanged)
// ---------------------------------------------------------------------------
__global__ void __launch_bounds__(256) kA(const float* __restrict__ psf) {
    const int b  = blockIdx.x;
    const int it = b & 7;
    const int c  = (b >> 3) & 31;
    const int n  = b >> 8;
    const int tid  = threadIdx.x;
    const int warp = tid >> 5;
    const int lane = tid & 31;
    const int ii   = warp >> 1;
    const int half = warp & 1;
    const int i = it * 4 + ii;

    const float4* base = (const float4*)(psf + ((size_t)(n * C_CH + c) * HW) * HW);
    const int r0 = 8 * i + 1 + 4 * half;
    const float4* p0 = base + r0 * (HW / 4);
    const float4* p1 = p0 + (HW / 4);

    float4 a0 = __ldg(p0 + lane);
    float4 a1 = __ldg(p0 + 32 + lane);
    float4 b0 = __ldg(p1 + lane);
    float4 b1 = __ldg(p1 + 32 + lane);

    float slo = (a0.y + a0.z) + (b0.y + b0.z);
    float shi = (a1.y + a1.z) + (b1.y + b1.z);
    slo = fmaxf(slo, __shfl_xor_sync(0xffffffffu, slo, 1));
    shi = fmaxf(shi, __shfl_xor_sync(0xffffffffu, shi, 1));

    __shared__ float sm[2][4][32];
    if ((lane & 1) == 0) {
        int j = lane >> 1;
        sm[half][ii][j]      = slo;
        sm[half][ii][j + 16] = shi;
    }
    __syncthreads();

    if (tid < 128) {
        int j  = tid & 31;
        int iw = tid >> 5;
        float m = fmaxf(sm[0][iw][j], sm[1][iw][j]);
        g_p[((size_t)(n * C_CH + c) * QS + it * 4 + iw) * QS + j] = 0.25f * m;
    }
}

// ---------------------------------------------------------------------------
// Kernel B (rewritten): block = (o-group of 32, pix-tile of 256, n).
// Stages p[32][256] (32KB) + weight slice (2x4KB) in smem; f32x2 over pixel
// pairs. Thread (lane, warp=osub): 4 pixel-pairs (u = lane+32i) x 4 o's.
// p L2 traffic: 147MB -> ~5MB; FMA instructions halved via FFMA2.
// ---------------------------------------------------------------------------
__global__ void __launch_bounds__(256) kB(const float* __restrict__ w1,
                                          const float* __restrict__ b1,
                                          const float* __restrict__ ws,
                                          const float* __restrict__ bs) {
    __shared__ float p_sm[C_CH][256];    // [c][pix within tile]
    __shared__ float w_sm1[32][32];      // [o local][c]
    __shared__ float w_sms[32][32];

    const int og    = blockIdx.x;        // 0..8
    const int ptile = blockIdx.y;        // 0..3
    const int n     = blockIdx.z;        // 0..3
    const int t     = threadIdx.x;
    const int lane  = t & 31;
    const int osub  = t >> 5;            // warp id 0..7

    // ---- stage p tile: 2048 float4, 8 per thread ----
    const float4* pg = (const float4*)(g_p + (size_t)n * (C_CH * QS * QS) + ptile * 256);
#pragma unroll
    for (int v = 0; v < 8; v++) {
        int idx = v * 256 + t;           // 0..2047
        int c  = idx >> 6;
        int f4 = idx & 63;
        *(float4*)&p_sm[c][4 * f4] = __ldg(pg + c * (1024 / 4) + f4);
    }
    // ---- stage weight slice: 256 float4 per array, 1 per thread ----
    {
        int ol = t >> 3;
        int cq = t & 7;
        *(float4*)&w_sm1[ol][4 * cq] = __ldg((const float4*)(w1 + (og * 32 + ol) * C_CH) + cq);
        *(float4*)&w_sms[ol][4 * cq] = __ldg((const float4*)(ws + (og * 32 + ol) * C_CH) + cq);
    }
    __syncthreads();

    // ---- accumulate: acc[m][i] over 32 channels ----
    u64 acc1[4][4], acc2[4][4];
#pragma unroll
    for (int m = 0; m < 4; m++)
#pragma unroll
        for (int i = 0; i < 4; i++) { acc1[m][i] = 0; acc2[m][i] = 0; }

#pragma unroll
    for (int c = 0; c < C_CH; c++) {
        u64 p2[4];
#pragma unroll
        for (int i = 0; i < 4; i++)
            p2[i] = *(const u64*)&p_sm[c][2 * (lane + 32 * i)];  // conflict-free
#pragma unroll
        for (int m = 0; m < 4; m++) {
            int ol = osub * 4 + m;
            float w1c = w_sm1[ol][c];    // broadcast LDS (warp-uniform ol)
            float wsc = w_sms[ol][c];
            u64 w12 = pk2(w1c, w1c);
            u64 ws2 = pk2(wsc, wsc);
#pragma unroll
            for (int i = 0; i < 4; i++) {
                acc1[m][i] = ffma2(w12, p2[i], acc1[m][i]);
                acc2[m][i] = ffma2(ws2, p2[i], acc2[m][i]);
            }
        }
    }

    // ---- epilogue: y = lrelu(dot1 + b1) + (dot2 + bs) ----
    float* yb = g_y + (size_t)n * (OCH * QS * QS) + (size_t)og * 32 * 1024 + ptile * 256;
#pragma unroll
    for (int m = 0; m < 4; m++) {
        int ol = osub * 4 + m;
        int o  = og * 32 + ol;
        float bb1 = __ldg(b1 + o);
        float bbs = __ldg(bs + o);
#pragma unroll
        for (int i = 0; i < 4; i++) {
            float2 d1 = unpk2(acc1[m][i]);
            float2 d2 = unpk2(acc2[m][i]);
            float z0 = d1.x + bb1, z1 = d1.y + bb1;
            float a0 = (z0 >= 0.f) ? z0 : 0.2f * z0;
            float a1 = (z1 >= 0.f) ? z1 : 0.2f * z1;
            float2 r = make_float2(a0 + d2.x + bbs, a1 + d2.y + bbs);
            *(float2*)&yb[ol * 1024 + 2 * (lane + 32 * i)] = r;
        }
    }
}

__global__ void kPad() {}

// ---------------------------------------------------------------------------
// Kernel C: f32x2 column-pair version (R10, unchanged)
// ---------------------------------------------------------------------------
__global__ void __launch_bounds__(128) kC(const float* __restrict__ fm,
                                          float* __restrict__ out) {
    __shared__ float fmt[18 * FSTR];
    __shared__ __align__(16) float yt[4][32][12];

    const int tt = blockIdx.x;
    const int c  = blockIdx.y;
    const int n  = blockIdx.z;
    const int j  = threadIdx.x;          // 0..127, columns (2j, 2j+1)
    const int h0 = tt * 16;
    const int crBase = 2 * tt - 1;

    const float4* fbase4 = (const float4*)(fm + ((size_t)(n * C_CH + c) * HW) * HW);
    const float4 z4 = make_float4(0.f, 0.f, 0.f, 0.f);
#pragma unroll
    for (int v = 0; v < 9; v++) {
        int idx = v * 128 + j;
        int r = idx >> 6;
        int q = idx & 63;
        int gh = h0 - 1 + r;
        float4 val = (gh >= 0 && gh < HW) ? __ldg(fbase4 + gh * (HW / 4) + q) : z4;
        *(float4*)&fmt[r * FSTR + 4 + 4 * q] = val;
    }
    if (j < 36) {
        int r = j >> 1;
        fmt[r * FSTR + 3 + 257 * (j & 1)] = 0.f;
    }

    const float* ybase = g_y + (size_t)(n * OCH + c * KS2) * (QS * QS);
#pragma unroll
    for (int v = 0; v < 3; v++) {
        int idx = v * 128 + j;
        if (idx < 288) {
            int q  = idx & 7;
            int rk = idx >> 3;
            int r  = rk / KS2;
            int k  = rk - r * KS2;
            int cr = min(max(crBase + r, 0), QS - 1);
            float4 s = __ldg((const float4*)(ybase + k * (QS * QS) + cr * QS) + q);
            int col = 4 * q;
            yt[r][col + 0][k] = s.x;
            yt[r][col + 1][k] = s.y;
            yt[r][col + 2][k] = s.z;
            yt[r][col + 3][k] = s.w;
        }
    }
    __syncthreads();

    const int c0 = 2 * j;
    int ix0 = (c0 - 4) >> 3;
    float wx0 = (float)c0 * 0.125f - 0.4375f - (float)ix0;
    float wx1 = wx0 + 0.125f;
    const int jx0 = max(ix0, 0);
    const int jx1 = min(ix0 + 1, QS - 1);

    u64 hl2[KS2], df2[KS2];
    auto loadHL2 = [&](int r, u64* dst) {
        const float4* pa = (const float4*)yt[r][jx0];
        const float4* pb = (const float4*)yt[r][jx1];
        float4 a0 = pa[0], a1 = pa[1];
        float4 b0 = pb[0], b1 = pb[1];
        float  a8 = yt[r][jx0][8];
        float  b8 = yt[r][jx1][8];
        float ta[KS2];
        ta[0] = b0.x - a0.x; ta[1] = b0.y - a0.y; ta[2] = b0.z - a0.z;
        ta[3] = b0.w - a0.w; ta[4] = b1.x - a1.x; ta[5] = b1.y - a1.y;
        ta[6] = b1.z - a1.z; ta[7] = b1.w - a1.w; ta[8] = b8 - a8;
        float av[KS2];
        av[0] = a0.x; av[1] = a0.y; av[2] = a0.z; av[3] = a0.w;
        av[4] = a1.x; av[5] = a1.y; av[6] = a1.z; av[7] = a1.w; av[8] = a8;
#pragma unroll
        for (int k = 0; k < KS2; k++)
            dst[k] = pk2(fmaf(wx0, ta[k], av[k]), fmaf(wx1, ta[k], av[k]));
    };

    loadHL2(0, hl2);
    loadHL2(1, df2);
#pragma unroll
    for (int k = 0; k < KS2; k++) df2[k] = fadd2(df2[k], fneg2(hl2[k]));

    auto advance = [&](int newRow) {
#pragma unroll
        for (int k = 0; k < KS2; k++) hl2[k] = fadd2(hl2[k], df2[k]);
        loadHL2(newRow, df2);
#pragma unroll
        for (int k = 0; k < KS2; k++) df2[k] = fadd2(df2[k], fneg2(hl2[k]));
    };

    const float* fcol = fmt + 3 + c0;
    u64 P[3][3];
#pragma unroll
    for (int r = 0; r < 2; r++) {
        float f0 = fcol[r * FSTR + 0], f1 = fcol[r * FSTR + 1];
        float f2 = fcol[r * FSTR + 2], f3 = fcol[r * FSTR + 3];
        P[r][0] = pk2(f0, f1); P[r][1] = pk2(f1, f2); P[r][2] = pk2(f2, f3);
    }

    float2* ob = (float2*)(out + (((size_t)(n * C_CH + c) * HW + h0) * HW) + c0);

    auto doRow = [&](int hh, float wy) {
        {
            float f0 = fcol[(hh + 2) * FSTR + 0], f1 = fcol[(hh + 2) * FSTR + 1];
            float f2 = fcol[(hh + 2) * FSTR + 2], f3 = fcol[(hh + 2) * FSTR + 3];
            P[2][0] = pk2(f0, f1); P[2][1] = pk2(f1, f2); P[2][2] = pk2(f2, f3);
        }
        u64 wy2 = pk2(wy, wy);
        u64 accA = 0, accB = 0;
#pragma unroll
        for (int dy = 0; dy < 3; dy++) {
#pragma unroll
            for (int dx = 0; dx < 3; dx++) {
                int k = dy * 3 + dx;
                u64 ft = ffma2(wy2, df2[k], hl2[k]);
                if (k < 5) accA = ffma2(ft, P[dy][dx], accA);
                else       accB = ffma2(ft, P[dy][dx], accB);
            }
        }
        ob[hh * (HW / 2)] = unpk2(fadd2(accA, accB));
#pragma unroll
        for (int d = 0; d < 3; d++) { P[0][d] = P[1][d]; P[1][d] = P[2][d]; }
    };

#pragma unroll
    for (int hh = 0; hh < 4; hh++)   doRow(hh, (float)hh * 0.125f + 0.5625f);
    advance(2);
#pragma unroll
    for (int hh = 4; hh < 12; hh++)  doRow(hh, (float)hh * 0.125f - 0.4375f);
    advance(3);
#pragma unroll
    for (int hh = 12; hh < 16; hh++) doRow(hh, (float)hh * 0.125f - 1.4375f);
}

// ---------------------------------------------------------------------------
extern "C" void kernel_launch(void* const* d_in, const int* in_sizes, int n_in,
                              void* d_out, int out_size) {
    const float* psf = (const float*)d_in[0];
    const float* fm  = (const float*)d_in[1];
    const float* w1  = (const float*)d_in[2];
    const float* b1  = (const float*)d_in[3];
    const float* ws  = (const float*)d_in[4];
    const float* bs  = (const float*)d_in[5];
    float* out = (float*)d_out;

    kA<<<1024, 256>>>(psf);
    dim3 gb(9, 4, NB);
    kB<<<gb, 256>>>(w1, b1, ws, bs);
    kPad<<<1, 32>>>();
    dim3 gc(16, C_CH, NB);
    kC<<<gc, 128>>>(fm, out);
}